// round 16
// baseline (speedup 1.0000x reference)
#include <cuda_runtime.h>
#include <math.h>

#define BB 2
#define LL 1024
#define DM 768
#define DI 1536
#define DS 16
#define DTR 48
#define XD 80              // DT_RANK + 2*D_STATE (logical)
#define XDP 128            // padded x_proj output width
#define KDT 64             // padded dt-proj K (wdt zero-padded 48->64)
#define MTOK (BB*LL)       // 2048 tokens
#define GSTG 3             // GEMM pipeline stages
#define BKK 32
#define SROW 36            // 32 + 4 pad, conflict-free
#define GEMM_SMEM (GSTG * 64 * SROW * 2 * 4)   // 55296 bytes
#define T_TILE 32
#define N_TILES (LL / T_TILE)

// ---------------- scratch (device globals; no allocation allowed) ----------------
__device__ __align__(128) float g_xz   [(size_t)BB*LL*2*DI];   // in_proj out, orig order
__device__ __align__(128) float g_xt   [(size_t)2*BB*LL*DI];   // conv+silu out (scan u, xproj A)
__device__ __align__(128) float g_xdbl [(size_t)2*BB*LL*XDP];  // x_proj out, padded width
__device__ __align__(128) float g_delta[(size_t)2*BB*LL*DI];   // softplus(dt proj)
__device__ __align__(128) float g_y    [(size_t)BB*LL*DI];     // y_f + y_r (atomic), orig order
__device__ __align__(128) float g_hs_r [(size_t)MTOK*DM];      // tf32-rounded hidden_states
__device__ __align__(128) float g_wi_r [(size_t)2*DI*DM];      // tf32-rounded in_proj_w
__device__ __align__(128) float g_wo_r [(size_t)DM*DI];        // tf32-rounded out_proj_w
__device__ __align__(128) float g_wxp  [(size_t)2*XDP*DI];     // padded+rounded x_proj_w (f,r)
__device__ __align__(128) float g_wdt  [(size_t)2*DI*KDT];     // padded+rounded dt_w (f,r)
__device__ __align__(128) float g_dtb  [(size_t)2*DI];         // dt bias (f,r), fp32

__device__ __forceinline__ float softplusf(float x) {
    return fmaxf(x, 0.f) + log1pf(expf(-fabsf(x)));
}
__device__ __forceinline__ float tf32r(float x) {
    unsigned u;
    asm("cvt.rna.tf32.f32 %0, %1;" : "=r"(u) : "f"(x));
    return __uint_as_float(u);
}

// ---------------- prep: tf32-round weights/inputs once; zero accumulators -------
__global__ void prep_kernel(
    const float* __restrict__ hs, const float* __restrict__ wi,
    const float* __restrict__ wo,
    const float* __restrict__ xpf, const float* __restrict__ xpr,
    const float* __restrict__ dtwf, const float* __restrict__ dtwr,
    const float* __restrict__ dtbf, const float* __restrict__ dtbr,
    float* __restrict__ hs_r, float* __restrict__ wi_r, float* __restrict__ wo_r,
    float* __restrict__ wxp, float* __restrict__ wdt, float* __restrict__ dtb,
    float* __restrict__ yz, float* __restrict__ xdblz, float* __restrict__ outz)
{
    int tid = blockIdx.x * blockDim.x + threadIdx.x;
    int stride = gridDim.x * blockDim.x;
    for (int i = tid; i < MTOK * DM; i += stride)       hs_r[i] = tf32r(hs[i]);
    for (int i = tid; i < 2 * DI * DM; i += stride)     wi_r[i] = tf32r(wi[i]);
    for (int i = tid; i < DM * DI; i += stride)         wo_r[i] = tf32r(wo[i]);
    for (int i = tid; i < 2 * XDP * DI; i += stride) {
        int k   = i % DI;
        int r   = (i / DI) % XDP;
        int dir = i / (XDP * DI);
        const float* src = dir ? xpr : xpf;
        wxp[i] = (r < XD) ? tf32r(src[(size_t)r * DI + k]) : 0.f;
    }
    for (int i = tid; i < 2 * DI * KDT; i += stride) {
        int k   = i % KDT;
        int n   = (i / KDT) % DI;
        int dir = i / (KDT * DI);
        const float* src = dir ? dtwr : dtwf;
        wdt[i] = (k < DTR) ? tf32r(src[(size_t)n * DTR + k]) : 0.f;
    }
    for (int i = tid; i < DI; i += stride) {
        dtb[i]      = dtbf[i];
        dtb[DI + i] = dtbr[i];
    }
    for (int i = tid; i < BB * LL * DI; i += stride)    yz[i] = 0.f;
    for (int i = tid; i < 2 * BB * LL * XDP; i += stride) xdblz[i] = 0.f;
    for (int i = tid; i < MTOK * DM; i += stride)       outz[i] = 0.f;
}

// ---------------- tf32 GEMM v3: 64x64x32 tiles, 128 thr, 3-stage cp.async -------
__global__ void __launch_bounds__(128, 4) tf32_gemm(
    const float* __restrict__ Ab, size_t Az,
    const float* __restrict__ Wb, size_t Wz,
    const float* __restrict__ biasb, size_t Bz,
    float* __restrict__ Cb, size_t Cz,
    int M, int N, int K, int lda, int act, int kslices)
{
    const int set  = blockIdx.z / kslices;
    const int kidx = blockIdx.z % kslices;
    const int Klen = K / kslices;
    const int Koff = kidx * Klen;

    const float* A = Ab + (size_t)set * Az;
    const float* W = Wb + (size_t)set * Wz;
    const float* bias = biasb ? biasb + (size_t)set * Bz : nullptr;
    float* C = Cb + (size_t)set * Cz;

    extern __shared__ float smem_dyn[];
    float (*As)[64][SROW] = (float(*)[64][SROW])smem_dyn;
    float (*Ws)[64][SROW] = (float(*)[64][SROW])(smem_dyn + GSTG * 64 * SROW);

    const int m0 = blockIdx.y * 64;
    const int n0 = blockIdx.x * 64;
    const int t    = threadIdx.x;
    const int lane = t & 31;
    const int wid  = t >> 5;
    const int wm   = wid & 1;
    const int wn   = wid >> 1;
    const int g    = lane >> 2;
    const int tg   = lane & 3;

    float acc[2][4][4];
    #pragma unroll
    for (int mt = 0; mt < 2; mt++)
        #pragma unroll
        for (int nt = 0; nt < 4; nt++)
            #pragma unroll
            for (int r = 0; r < 4; r++) acc[mt][nt][r] = 0.f;

    const int nIter = Klen / BKK;

    auto load_stage = [&](int s, int k0) {
        #pragma unroll
        for (int it = 0; it < 4; it++) {
            int c = t + it * 128;
            int row = c >> 3;
            int kc  = (c & 7) << 2;
            unsigned da = (unsigned)__cvta_generic_to_shared(&As[s][row][kc]);
            const float* sa = A + (size_t)(m0 + row) * lda + Koff + k0 + kc;
            asm volatile("cp.async.cg.shared.global [%0], [%1], 16;\n"
                         :: "r"(da), "l"(sa));
            unsigned dw = (unsigned)__cvta_generic_to_shared(&Ws[s][row][kc]);
            const float* sw = W + (size_t)(n0 + row) * K + Koff + k0 + kc;
            asm volatile("cp.async.cg.shared.global [%0], [%1], 16;\n"
                         :: "r"(dw), "l"(sw));
        }
        asm volatile("cp.async.commit_group;\n" ::);
    };

    #pragma unroll
    for (int p = 0; p < GSTG - 1; p++)
        if (p < nIter) load_stage(p, p * BKK);

    for (int i = 0; i < nIter; i++) {
        int s = i % GSTG;
        int rem = nIter - i - 1;
        if (rem >= 1) asm volatile("cp.async.wait_group 1;\n" ::);
        else          asm volatile("cp.async.wait_group 0;\n" ::);
        __syncthreads();

        #pragma unroll
        for (int ks = 0; ks < BKK; ks += 8) {
            unsigned a[2][4], bfr[4][2];
            #pragma unroll
            for (int mt = 0; mt < 2; mt++) {
                int mr = wm * 32 + mt * 16 + g;
                a[mt][0] = __float_as_uint(As[s][mr    ][ks + tg]);
                a[mt][1] = __float_as_uint(As[s][mr + 8][ks + tg]);
                a[mt][2] = __float_as_uint(As[s][mr    ][ks + tg + 4]);
                a[mt][3] = __float_as_uint(As[s][mr + 8][ks + tg + 4]);
            }
            #pragma unroll
            for (int nt = 0; nt < 4; nt++) {
                int nc = wn * 32 + nt * 8 + g;
                bfr[nt][0] = __float_as_uint(Ws[s][nc][ks + tg]);
                bfr[nt][1] = __float_as_uint(Ws[s][nc][ks + tg + 4]);
            }
            #pragma unroll
            for (int mt = 0; mt < 2; mt++)
                #pragma unroll
                for (int nt = 0; nt < 4; nt++) {
                    asm volatile(
                        "mma.sync.aligned.m16n8k8.row.col.f32.tf32.tf32.f32 "
                        "{%0,%1,%2,%3}, {%4,%5,%6,%7}, {%8,%9}, {%0,%1,%2,%3};"
                        : "+f"(acc[mt][nt][0]), "+f"(acc[mt][nt][1]),
                          "+f"(acc[mt][nt][2]), "+f"(acc[mt][nt][3])
                        : "r"(a[mt][0]), "r"(a[mt][1]), "r"(a[mt][2]), "r"(a[mt][3]),
                          "r"(bfr[nt][0]), "r"(bfr[nt][1]));
                }
        }
        __syncthreads();
        int nl = i + GSTG - 1;
        if (nl < nIter) load_stage(nl % GSTG, nl * BKK);
    }

    #pragma unroll
    for (int mt = 0; mt < 2; mt++) {
        int r0 = m0 + wm * 32 + mt * 16 + g;
        #pragma unroll
        for (int nt = 0; nt < 4; nt++) {
            int c0 = n0 + wn * 32 + nt * 8 + 2 * tg;
            float v0 = acc[mt][nt][0], v1 = acc[mt][nt][1];
            float v2 = acc[mt][nt][2], v3 = acc[mt][nt][3];
            if (kslices > 1) {
                atomicAdd(C + (size_t)r0 * N + c0,           v0);
                atomicAdd(C + (size_t)r0 * N + c0 + 1,       v1);
                atomicAdd(C + (size_t)(r0 + 8) * N + c0,     v2);
                atomicAdd(C + (size_t)(r0 + 8) * N + c0 + 1, v3);
            } else {
                if (bias) {
                    float b0 = bias[c0], b1 = bias[c0 + 1];
                    v0 += b0; v1 += b1; v2 += b0; v3 += b1;
                }
                if (act == 1) {
                    v0 = softplusf(v0); v1 = softplusf(v1);
                    v2 = softplusf(v2); v3 = softplusf(v3);
                }
                *(float2*)(C + (size_t)r0 * N + c0)       = make_float2(v0, v1);
                *(float2*)(C + (size_t)(r0 + 8) * N + c0) = make_float2(v2, v3);
            }
        }
    }
}

// ---------------- depthwise causal conv1d + silu, both directions ----------------
__global__ void conv_silu_kernel(
    const float* __restrict__ xz,
    const float* __restrict__ cwf, const float* __restrict__ cbf,
    const float* __restrict__ cwr, const float* __restrict__ cbr,
    float* __restrict__ xt)
{
    long idx = (long)blockIdx.x * blockDim.x + threadIdx.x;
    if (idx >= (long)2 * BB * LL * DI) return;
    int d   = (int)(idx % DI);
    int p   = (int)((idx / DI) % LL);
    int b   = (int)((idx / ((long)DI * LL)) % BB);
    int dir = (int)(idx / ((long)DI * LL * BB));

    const float* cw = dir ? cwr : cwf;
    const float* cb = dir ? cbr : cbf;
    float4 w4 = *(const float4*)(cw + d * 4);
    float wv[4] = {w4.x, w4.y, w4.z, w4.w};

    float acc = cb[d];
    const float* xbase = xz + (size_t)b * LL * 2 * DI + d;
    #pragma unroll
    for (int j = 0; j < 4; j++) {
        int q = p - 3 + j;
        if (q >= 0) {
            int ol = dir ? (LL - 1 - q) : q;
            acc = fmaf(wv[j], xbase[(size_t)ol * 2 * DI], acc);
        }
    }
    xt[idx] = acc / (1.f + __expf(-acc));   // silu
}

// ---------------- selective scan v3: smem-staged + exp hoisted off critical path --
// Phase 1 per tile: precompute dA[32], dtu[32] (independent of h, MUFU pipelined).
// Phase 2: serial recurrence h = fmaf(dA, h, dtu*Bv) — critical path = 1 fmaf/step.
__global__ void __launch_bounds__(128) scan_kernel(
    const float* __restrict__ xz,   const float* __restrict__ xt,
    const float* __restrict__ xdbl, const float* __restrict__ delta,
    const float* __restrict__ Alog_f, const float* __restrict__ Df,
    const float* __restrict__ Alog_r, const float* __restrict__ Dr,
    float* __restrict__ y)
{
    __shared__ float sdt[2][T_TILE][8];
    __shared__ float su [2][T_TILE][8];
    __shared__ float sz [2][T_TILE][8];
    __shared__ float sBC[2][T_TILE][32];

    const int dir  = blockIdx.z, b = blockIdx.y;
    const int tid  = threadIdx.x;
    const int warp = tid >> 5, lane = tid & 31;
    const int half = (lane >> 4) & 1, n = lane & 15;
    const int ch   = warp * 2 + half;           // 0..7 channel within block
    const int d0   = blockIdx.x * 8;
    const int d    = d0 + ch;

    const float* Alog = dir ? Alog_r : Alog_f;
    const float* Dp   = dir ? Dr     : Df;
    const float Acoef = -expf(Alog[d * DS + n]);
    const float Dd    = Dp[d];

    const float* dbase = delta + ((size_t)(dir * BB + b) * LL) * DI + d0;
    const float* ubase = xt    + ((size_t)(dir * BB + b) * LL) * DI + d0;
    const float* xb    = xdbl  + ((size_t)(dir * BB + b) * LL) * XDP;
    const float* zb    = xz    + (size_t)b * LL * 2 * DI + DI + d0;
    float*       yb    = y     + (size_t)b * LL * DI + d0;

    auto prefetch = [&](int tile, int buf) {
        int t0 = tile * T_TILE;
        for (int c = tid; c < 448; c += 128) {
            if (c < 64) {
                int row = c >> 1, h4 = (c & 1) << 2;
                unsigned dst = (unsigned)__cvta_generic_to_shared(&sdt[buf][row][h4]);
                asm volatile("cp.async.cg.shared.global [%0], [%1], 16;\n"
                             :: "r"(dst), "l"(dbase + (size_t)(t0 + row) * DI + h4));
            } else if (c < 128) {
                int cc = c - 64, row = cc >> 1, h4 = (cc & 1) << 2;
                unsigned dst = (unsigned)__cvta_generic_to_shared(&su[buf][row][h4]);
                asm volatile("cp.async.cg.shared.global [%0], [%1], 16;\n"
                             :: "r"(dst), "l"(ubase + (size_t)(t0 + row) * DI + h4));
            } else if (c < 192) {
                int cc = c - 128, row = cc >> 1, h4 = (cc & 1) << 2;
                int ol = dir ? (LL - 1 - (t0 + row)) : (t0 + row);
                unsigned dst = (unsigned)__cvta_generic_to_shared(&sz[buf][row][h4]);
                asm volatile("cp.async.cg.shared.global [%0], [%1], 16;\n"
                             :: "r"(dst), "l"(zb + (size_t)ol * 2 * DI + h4));
            } else {
                int cc = c - 192, row = cc >> 3, k4 = (cc & 7) << 2;
                unsigned dst = (unsigned)__cvta_generic_to_shared(&sBC[buf][row][k4]);
                asm volatile("cp.async.cg.shared.global [%0], [%1], 16;\n"
                             :: "r"(dst), "l"(xb + (size_t)(t0 + row) * XDP + DTR + k4));
            }
        }
        asm volatile("cp.async.commit_group;\n" ::);
    };

    prefetch(0, 0);

    float h = 0.f;
    for (int tile = 0; tile < N_TILES; tile++) {
        int buf = tile & 1;
        if (tile + 1 < N_TILES) {
            prefetch(tile + 1, buf ^ 1);
            asm volatile("cp.async.wait_group 1;\n" ::);
        } else {
            asm volatile("cp.async.wait_group 0;\n" ::);
        }
        __syncthreads();

        // phase 1: precompute dA and dt*u for all 32 steps (off critical path)
        float dA[T_TILE], dtu[T_TILE];
        #pragma unroll
        for (int tt = 0; tt < T_TILE; tt++) {
            float dt_ = sdt[buf][tt][ch];
            float u   = su [buf][tt][ch];
            dA[tt]  = __expf(dt_ * Acoef);
            dtu[tt] = dt_ * u;
        }

        // phase 2: serial recurrence (critical path = one fmaf per step)
        #pragma unroll
        for (int tt = 0; tt < T_TILE; tt++) {
            float Bv  = sBC[buf][tt][n];
            float Cv  = sBC[buf][tt][16 + n];
            h = fmaf(dA[tt], h, dtu[tt] * Bv);
            float part = h * Cv;
            part += __shfl_down_sync(0xffffffffu, part, 8, 16);
            part += __shfl_down_sync(0xffffffffu, part, 4, 16);
            part += __shfl_down_sync(0xffffffffu, part, 2, 16);
            part += __shfl_down_sync(0xffffffffu, part, 1, 16);
            if (n == 0) {
                int t  = tile * T_TILE + tt;
                int ol = dir ? (LL - 1 - t) : t;
                float zv = sz[buf][tt][ch];
                float u  = su[buf][tt][ch];
                float yv = part + Dd * u;
                float sg = zv / (1.f + __expf(-zv));   // silu(z)
                atomicAdd(&yb[(size_t)ol * DI + ch], yv * sg);
            }
        }
        __syncthreads();
    }
}

// ---------------- launch ----------------
extern "C" void kernel_launch(void* const* d_in, const int* in_sizes, int n_in,
                              void* d_out, int out_size)
{
    const float* hs   = (const float*)d_in[0];
    const float* wi   = (const float*)d_in[1];
    const float* wo   = (const float*)d_in[2];
    const float* cwf  = (const float*)d_in[3];
    const float* cbf  = (const float*)d_in[4];
    const float* xpf  = (const float*)d_in[5];
    const float* dtwf = (const float*)d_in[6];
    const float* dtbf = (const float*)d_in[7];
    const float* alf  = (const float*)d_in[8];
    const float* Dfp  = (const float*)d_in[9];
    const float* cwr  = (const float*)d_in[10];
    const float* cbr  = (const float*)d_in[11];
    const float* xpr  = (const float*)d_in[12];
    const float* dtwr = (const float*)d_in[13];
    const float* dtbr = (const float*)d_in[14];
    const float* alr  = (const float*)d_in[15];
    const float* Drp  = (const float*)d_in[16];
    float* out = (float*)d_out;

    float *xz, *xt, *xdbl, *delta, *y, *hs_r, *wi_r, *wo_r, *wxp, *wdt, *dtb;
    cudaGetSymbolAddress((void**)&xz,    g_xz);
    cudaGetSymbolAddress((void**)&xt,    g_xt);
    cudaGetSymbolAddress((void**)&xdbl,  g_xdbl);
    cudaGetSymbolAddress((void**)&delta, g_delta);
    cudaGetSymbolAddress((void**)&y,     g_y);
    cudaGetSymbolAddress((void**)&hs_r,  g_hs_r);
    cudaGetSymbolAddress((void**)&wi_r,  g_wi_r);
    cudaGetSymbolAddress((void**)&wo_r,  g_wo_r);
    cudaGetSymbolAddress((void**)&wxp,   g_wxp);
    cudaGetSymbolAddress((void**)&wdt,   g_wdt);
    cudaGetSymbolAddress((void**)&dtb,   g_dtb);

    cudaFuncSetAttribute(tf32_gemm,
                         cudaFuncAttributeMaxDynamicSharedMemorySize, GEMM_SMEM);

    const size_t dir_di = (size_t)BB * LL * DI;
    const size_t dir_xp = (size_t)BB * LL * XDP;

    // 0. prep (incl. zero-padded dt weights K=64)
    prep_kernel<<<2048, 256>>>(hs, wi, wo, xpf, xpr, dtwf, dtwr, dtbf, dtbr,
                               hs_r, wi_r, wo_r, wxp, wdt, dtb, y, xdbl, out);

    // 1. shared in_proj: xz = hs @ wi^T  (2048 x 3072 x 768)
    tf32_gemm<<<dim3(2 * DI / 64, MTOK / 64, 1), 128, GEMM_SMEM>>>(
        hs_r, 0, wi_r, 0, nullptr, 0, xz, 0, MTOK, 2 * DI, DM, DM, 0, 1);

    // 2. depthwise conv + silu, both dirs
    long total = (long)2 * BB * LL * DI;
    conv_silu_kernel<<<(unsigned)((total + 255) / 256), 256>>>(
        xz, cwf, cbf, cwr, cbr, xt);

    // 3. x_proj, padded N=128, both dirs, split-K x4
    tf32_gemm<<<dim3(XDP / 64, MTOK / 64, 2 * 4), 128, GEMM_SMEM>>>(
        xt, dir_di, wxp, (size_t)XDP * DI, nullptr, 0,
        xdbl, dir_xp, MTOK, XDP, DI, DI, 0, 4);

    // 4. dt projection + softplus, both dirs (K padded to 64, lda=128)
    tf32_gemm<<<dim3(DI / 64, MTOK / 64, 2), 128, GEMM_SMEM>>>(
        xdbl, dir_xp, wdt, (size_t)DI * KDT, dtb, (size_t)DI,
        delta, dir_di, MTOK, DI, KDT, XDP, 1, 1);

    // 5. selective scan v3 (exp hoisted) + gate; atomic y_f + y_r
    scan_kernel<<<dim3(DI / 8, BB, 2), 128>>>(
        xz, xt, xdbl, delta, alf, Dfp, alr, Drp, y);

    // 6. shared out_proj on accumulated y, split-K x3
    tf32_gemm<<<dim3(DM / 64, MTOK / 64, 3), 128, GEMM_SMEM>>>(
        y, 0, wo_r, 0, nullptr, 0, out, 0, MTOK, DM, DI, DI, 0, 3);
}

// round 17
// speedup vs baseline: 1.8651x; 1.8651x over previous
#include <cuda_runtime.h>
#include <math.h>

#define BB 2
#define LL 1024
#define DM 768
#define DI 1536
#define DS 16
#define DTR 48
#define XD 80              // DT_RANK + 2*D_STATE (logical)
#define XDP 128            // padded x_proj output width
#define KDT 64             // padded dt-proj K (wdt zero-padded 48->64)
#define MTOK (BB*LL)       // 2048 tokens
#define GSTG 3             // GEMM pipeline stages
#define BKK 32
#define SROW 36            // 32 + 4 pad, conflict-free
#define GEMM_SMEM (GSTG * 64 * SROW * 2 * 4)   // 55296 bytes
#define T_TILE 32
#define N_TILES (LL / T_TILE)

// ---------------- scratch (device globals; no allocation allowed) ----------------
__device__ __align__(128) float g_xz   [(size_t)BB*LL*2*DI];   // in_proj out, orig order
__device__ __align__(128) float g_xt   [(size_t)2*BB*LL*DI];   // conv+silu out (scan u, xproj A)
__device__ __align__(128) float g_xdbl [(size_t)2*BB*LL*XDP];  // x_proj out, padded width
__device__ __align__(128) float g_delta[(size_t)2*BB*LL*DI];   // softplus(dt proj)
__device__ __align__(128) float g_y    [(size_t)BB*LL*DI];     // y_f + y_r (atomic), orig order
__device__ __align__(128) float g_hs_r [(size_t)MTOK*DM];      // tf32-rounded hidden_states
__device__ __align__(128) float g_wi_r [(size_t)2*DI*DM];      // tf32-rounded in_proj_w
__device__ __align__(128) float g_wo_r [(size_t)DM*DI];        // tf32-rounded out_proj_w
__device__ __align__(128) float g_wxp  [(size_t)2*XDP*DI];     // padded+rounded x_proj_w (f,r)
__device__ __align__(128) float g_wdt  [(size_t)2*DI*KDT];     // padded+rounded dt_w (f,r)
__device__ __align__(128) float g_dtb  [(size_t)2*DI];         // dt bias (f,r), fp32

__device__ __forceinline__ float softplusf(float x) {
    return fmaxf(x, 0.f) + log1pf(expf(-fabsf(x)));
}
__device__ __forceinline__ float tf32r(float x) {
    unsigned u;
    asm("cvt.rna.tf32.f32 %0, %1;" : "=r"(u) : "f"(x));
    return __uint_as_float(u);
}

// ---------------- prep: tf32-round weights/inputs once; zero accumulators -------
__global__ void prep_kernel(
    const float* __restrict__ hs, const float* __restrict__ wi,
    const float* __restrict__ wo,
    const float* __restrict__ xpf, const float* __restrict__ xpr,
    const float* __restrict__ dtwf, const float* __restrict__ dtwr,
    const float* __restrict__ dtbf, const float* __restrict__ dtbr,
    float* __restrict__ hs_r, float* __restrict__ wi_r, float* __restrict__ wo_r,
    float* __restrict__ wxp, float* __restrict__ wdt, float* __restrict__ dtb,
    float* __restrict__ yz, float* __restrict__ xdblz, float* __restrict__ outz)
{
    int tid = blockIdx.x * blockDim.x + threadIdx.x;
    int stride = gridDim.x * blockDim.x;
    for (int i = tid; i < MTOK * DM; i += stride)       hs_r[i] = tf32r(hs[i]);
    for (int i = tid; i < 2 * DI * DM; i += stride)     wi_r[i] = tf32r(wi[i]);
    for (int i = tid; i < DM * DI; i += stride)         wo_r[i] = tf32r(wo[i]);
    for (int i = tid; i < 2 * XDP * DI; i += stride) {
        int k   = i % DI;
        int r   = (i / DI) % XDP;
        int dir = i / (XDP * DI);
        const float* src = dir ? xpr : xpf;
        wxp[i] = (r < XD) ? tf32r(src[(size_t)r * DI + k]) : 0.f;
    }
    for (int i = tid; i < 2 * DI * KDT; i += stride) {
        int k   = i % KDT;
        int n   = (i / KDT) % DI;
        int dir = i / (KDT * DI);
        const float* src = dir ? dtwr : dtwf;
        wdt[i] = (k < DTR) ? tf32r(src[(size_t)n * DTR + k]) : 0.f;
    }
    for (int i = tid; i < DI; i += stride) {
        dtb[i]      = dtbf[i];
        dtb[DI + i] = dtbr[i];
    }
    for (int i = tid; i < BB * LL * DI; i += stride)    yz[i] = 0.f;
    for (int i = tid; i < 2 * BB * LL * XDP; i += stride) xdblz[i] = 0.f;
    for (int i = tid; i < MTOK * DM; i += stride)       outz[i] = 0.f;
}

// ---------------- tf32 GEMM v3: 64x64x32 tiles, 128 thr, 3-stage cp.async -------
__global__ void __launch_bounds__(128, 4) tf32_gemm(
    const float* __restrict__ Ab, size_t Az,
    const float* __restrict__ Wb, size_t Wz,
    const float* __restrict__ biasb, size_t Bz,
    float* __restrict__ Cb, size_t Cz,
    int M, int N, int K, int lda, int act, int kslices)
{
    const int set  = blockIdx.z / kslices;
    const int kidx = blockIdx.z % kslices;
    const int Klen = K / kslices;
    const int Koff = kidx * Klen;

    const float* A = Ab + (size_t)set * Az;
    const float* W = Wb + (size_t)set * Wz;
    const float* bias = biasb ? biasb + (size_t)set * Bz : nullptr;
    float* C = Cb + (size_t)set * Cz;

    extern __shared__ float smem_dyn[];
    float (*As)[64][SROW] = (float(*)[64][SROW])smem_dyn;
    float (*Ws)[64][SROW] = (float(*)[64][SROW])(smem_dyn + GSTG * 64 * SROW);

    const int m0 = blockIdx.y * 64;
    const int n0 = blockIdx.x * 64;
    const int t    = threadIdx.x;
    const int lane = t & 31;
    const int wid  = t >> 5;
    const int wm   = wid & 1;
    const int wn   = wid >> 1;
    const int g    = lane >> 2;
    const int tg   = lane & 3;

    float acc[2][4][4];
    #pragma unroll
    for (int mt = 0; mt < 2; mt++)
        #pragma unroll
        for (int nt = 0; nt < 4; nt++)
            #pragma unroll
            for (int r = 0; r < 4; r++) acc[mt][nt][r] = 0.f;

    const int nIter = Klen / BKK;

    auto load_stage = [&](int s, int k0) {
        #pragma unroll
        for (int it = 0; it < 4; it++) {
            int c = t + it * 128;
            int row = c >> 3;
            int kc  = (c & 7) << 2;
            unsigned da = (unsigned)__cvta_generic_to_shared(&As[s][row][kc]);
            const float* sa = A + (size_t)(m0 + row) * lda + Koff + k0 + kc;
            asm volatile("cp.async.cg.shared.global [%0], [%1], 16;\n"
                         :: "r"(da), "l"(sa));
            unsigned dw = (unsigned)__cvta_generic_to_shared(&Ws[s][row][kc]);
            const float* sw = W + (size_t)(n0 + row) * K + Koff + k0 + kc;
            asm volatile("cp.async.cg.shared.global [%0], [%1], 16;\n"
                         :: "r"(dw), "l"(sw));
        }
        asm volatile("cp.async.commit_group;\n" ::);
    };

    #pragma unroll
    for (int p = 0; p < GSTG - 1; p++)
        if (p < nIter) load_stage(p, p * BKK);

    for (int i = 0; i < nIter; i++) {
        int s = i % GSTG;
        int rem = nIter - i - 1;
        if (rem >= 1) asm volatile("cp.async.wait_group 1;\n" ::);
        else          asm volatile("cp.async.wait_group 0;\n" ::);
        __syncthreads();

        #pragma unroll
        for (int ks = 0; ks < BKK; ks += 8) {
            unsigned a[2][4], bfr[4][2];
            #pragma unroll
            for (int mt = 0; mt < 2; mt++) {
                int mr = wm * 32 + mt * 16 + g;
                a[mt][0] = __float_as_uint(As[s][mr    ][ks + tg]);
                a[mt][1] = __float_as_uint(As[s][mr + 8][ks + tg]);
                a[mt][2] = __float_as_uint(As[s][mr    ][ks + tg + 4]);
                a[mt][3] = __float_as_uint(As[s][mr + 8][ks + tg + 4]);
            }
            #pragma unroll
            for (int nt = 0; nt < 4; nt++) {
                int nc = wn * 32 + nt * 8 + g;
                bfr[nt][0] = __float_as_uint(Ws[s][nc][ks + tg]);
                bfr[nt][1] = __float_as_uint(Ws[s][nc][ks + tg + 4]);
            }
            #pragma unroll
            for (int mt = 0; mt < 2; mt++)
                #pragma unroll
                for (int nt = 0; nt < 4; nt++) {
                    asm volatile(
                        "mma.sync.aligned.m16n8k8.row.col.f32.tf32.tf32.f32 "
                        "{%0,%1,%2,%3}, {%4,%5,%6,%7}, {%8,%9}, {%0,%1,%2,%3};"
                        : "+f"(acc[mt][nt][0]), "+f"(acc[mt][nt][1]),
                          "+f"(acc[mt][nt][2]), "+f"(acc[mt][nt][3])
                        : "r"(a[mt][0]), "r"(a[mt][1]), "r"(a[mt][2]), "r"(a[mt][3]),
                          "r"(bfr[nt][0]), "r"(bfr[nt][1]));
                }
        }
        __syncthreads();
        int nl = i + GSTG - 1;
        if (nl < nIter) load_stage(nl % GSTG, nl * BKK);
    }

    #pragma unroll
    for (int mt = 0; mt < 2; mt++) {
        int r0 = m0 + wm * 32 + mt * 16 + g;
        #pragma unroll
        for (int nt = 0; nt < 4; nt++) {
            int c0 = n0 + wn * 32 + nt * 8 + 2 * tg;
            float v0 = acc[mt][nt][0], v1 = acc[mt][nt][1];
            float v2 = acc[mt][nt][2], v3 = acc[mt][nt][3];
            if (kslices > 1) {
                atomicAdd(C + (size_t)r0 * N + c0,           v0);
                atomicAdd(C + (size_t)r0 * N + c0 + 1,       v1);
                atomicAdd(C + (size_t)(r0 + 8) * N + c0,     v2);
                atomicAdd(C + (size_t)(r0 + 8) * N + c0 + 1, v3);
            } else {
                if (bias) {
                    float b0 = bias[c0], b1 = bias[c0 + 1];
                    v0 += b0; v1 += b1; v2 += b0; v3 += b1;
                }
                if (act == 1) {
                    v0 = softplusf(v0); v1 = softplusf(v1);
                    v2 = softplusf(v2); v3 = softplusf(v3);
                }
                *(float2*)(C + (size_t)r0 * N + c0)       = make_float2(v0, v1);
                *(float2*)(C + (size_t)(r0 + 8) * N + c0) = make_float2(v2, v3);
            }
        }
    }
}

// ---------------- depthwise causal conv1d + silu, both directions ----------------
__global__ void conv_silu_kernel(
    const float* __restrict__ xz,
    const float* __restrict__ cwf, const float* __restrict__ cbf,
    const float* __restrict__ cwr, const float* __restrict__ cbr,
    float* __restrict__ xt)
{
    long idx = (long)blockIdx.x * blockDim.x + threadIdx.x;
    if (idx >= (long)2 * BB * LL * DI) return;
    int d   = (int)(idx % DI);
    int p   = (int)((idx / DI) % LL);
    int b   = (int)((idx / ((long)DI * LL)) % BB);
    int dir = (int)(idx / ((long)DI * LL * BB));

    const float* cw = dir ? cwr : cwf;
    const float* cb = dir ? cbr : cbf;
    float4 w4 = *(const float4*)(cw + d * 4);
    float wv[4] = {w4.x, w4.y, w4.z, w4.w};

    float acc = cb[d];
    const float* xbase = xz + (size_t)b * LL * 2 * DI + d;
    #pragma unroll
    for (int j = 0; j < 4; j++) {
        int q = p - 3 + j;
        if (q >= 0) {
            int ol = dir ? (LL - 1 - q) : q;
            acc = fmaf(wv[j], xbase[(size_t)ol * 2 * DI], acc);
        }
    }
    xt[idx] = acc / (1.f + __expf(-acc));   // silu
}

// ---------------- selective scan v4: smem partials, no shfl in serial loop -------
// Serial phase: h = fmaf(dA, h, dtu*Bv); STS h*Cv (off critical path).
// Phase B: per-warp vectorized 16-state sums from smem + gate + atomic.
// Exp hoisted in batches of 8 (bounded register pressure).
__global__ void __launch_bounds__(128) scan_kernel(
    const float* __restrict__ xz,   const float* __restrict__ xt,
    const float* __restrict__ xdbl, const float* __restrict__ delta,
    const float* __restrict__ Alog_f, const float* __restrict__ Df,
    const float* __restrict__ Alog_r, const float* __restrict__ Dr,
    float* __restrict__ y)
{
    __shared__ float sdt[2][T_TILE][8];
    __shared__ float su [2][T_TILE][8];
    __shared__ float sz [2][T_TILE][8];
    __shared__ float sBC[2][T_TILE][32];
    __shared__ float sp [8][16][T_TILE + 1];   // [ch][state][step], pad vs conflicts
    __shared__ float sD [8];

    const int dir  = blockIdx.z, b = blockIdx.y;
    const int tid  = threadIdx.x;
    const int warp = tid >> 5, lane = tid & 31;
    const int half = (lane >> 4) & 1, n = lane & 15;
    const int ch   = warp * 2 + half;           // 0..7 channel within block
    const int d0   = blockIdx.x * 8;
    const int d    = d0 + ch;

    const float* Alog = dir ? Alog_r : Alog_f;
    const float* Dp   = dir ? Dr     : Df;
    const float Acoef = -expf(Alog[d * DS + n]);

    if (tid < 8) sD[tid] = Dp[d0 + tid];

    const float* dbase = delta + ((size_t)(dir * BB + b) * LL) * DI + d0;
    const float* ubase = xt    + ((size_t)(dir * BB + b) * LL) * DI + d0;
    const float* xb    = xdbl  + ((size_t)(dir * BB + b) * LL) * XDP;
    const float* zb    = xz    + (size_t)b * LL * 2 * DI + DI + d0;
    float*       yb    = y     + (size_t)b * LL * DI + d0;

    auto prefetch = [&](int tile, int buf) {
        int t0 = tile * T_TILE;
        for (int c = tid; c < 448; c += 128) {
            if (c < 64) {
                int row = c >> 1, h4 = (c & 1) << 2;
                unsigned dst = (unsigned)__cvta_generic_to_shared(&sdt[buf][row][h4]);
                asm volatile("cp.async.cg.shared.global [%0], [%1], 16;\n"
                             :: "r"(dst), "l"(dbase + (size_t)(t0 + row) * DI + h4));
            } else if (c < 128) {
                int cc = c - 64, row = cc >> 1, h4 = (cc & 1) << 2;
                unsigned dst = (unsigned)__cvta_generic_to_shared(&su[buf][row][h4]);
                asm volatile("cp.async.cg.shared.global [%0], [%1], 16;\n"
                             :: "r"(dst), "l"(ubase + (size_t)(t0 + row) * DI + h4));
            } else if (c < 192) {
                int cc = c - 128, row = cc >> 1, h4 = (cc & 1) << 2;
                int ol = dir ? (LL - 1 - (t0 + row)) : (t0 + row);
                unsigned dst = (unsigned)__cvta_generic_to_shared(&sz[buf][row][h4]);
                asm volatile("cp.async.cg.shared.global [%0], [%1], 16;\n"
                             :: "r"(dst), "l"(zb + (size_t)ol * 2 * DI + h4));
            } else {
                int cc = c - 192, row = cc >> 3, k4 = (cc & 7) << 2;
                unsigned dst = (unsigned)__cvta_generic_to_shared(&sBC[buf][row][k4]);
                asm volatile("cp.async.cg.shared.global [%0], [%1], 16;\n"
                             :: "r"(dst), "l"(xb + (size_t)(t0 + row) * XDP + DTR + k4));
            }
        }
        asm volatile("cp.async.commit_group;\n" ::);
    };

    prefetch(0, 0);

    float h = 0.f;
    for (int tile = 0; tile < N_TILES; tile++) {
        int buf = tile & 1;
        if (tile + 1 < N_TILES) {
            prefetch(tile + 1, buf ^ 1);
            asm volatile("cp.async.wait_group 1;\n" ::);
        } else {
            asm volatile("cp.async.wait_group 0;\n" ::);
        }
        __syncthreads();

        // serial phase: 4 sub-batches of 8 (exp hoisted per sub-batch)
        #pragma unroll
        for (int sub = 0; sub < 4; sub++) {
            float dA[8], dtu[8];
            #pragma unroll
            for (int j = 0; j < 8; j++) {
                int tt = sub * 8 + j;
                float dt_ = sdt[buf][tt][ch];
                float u   = su [buf][tt][ch];
                dA[j]  = __expf(dt_ * Acoef);
                dtu[j] = dt_ * u;
            }
            #pragma unroll
            for (int j = 0; j < 8; j++) {
                int tt = sub * 8 + j;
                float Bv = sBC[buf][tt][n];
                float Cv = sBC[buf][tt][16 + n];
                h = fmaf(dA[j], h, dtu[j] * Bv);
                sp[ch][n][tt] = h * Cv;     // STS: off the h critical path
            }
        }
        __syncwarp();

        // phase B: per warp, 2 channels x 32 steps; 2 sums of 16 per lane
        #pragma unroll
        for (int r = 0; r < 2; r++) {
            int idx = r * 32 + lane;
            int tt  = idx & 31;
            int c2  = idx >> 5;
            int ch2 = warp * 2 + c2;
            float s = 0.f;
            #pragma unroll
            for (int nn = 0; nn < 16; nn++) s += sp[ch2][nn][tt];
            int tg = tile * T_TILE + tt;
            int ol = dir ? (LL - 1 - tg) : tg;
            float u  = su[buf][tt][ch2];
            float zv = sz[buf][tt][ch2];
            float yv = s + sD[ch2] * u;
            float sg = zv / (1.f + __expf(-zv));   // silu(z)
            atomicAdd(&yb[(size_t)ol * DI + ch2], yv * sg);
        }
        __syncthreads();
    }
}

// ---------------- launch ----------------
extern "C" void kernel_launch(void* const* d_in, const int* in_sizes, int n_in,
                              void* d_out, int out_size)
{
    const float* hs   = (const float*)d_in[0];
    const float* wi   = (const float*)d_in[1];
    const float* wo   = (const float*)d_in[2];
    const float* cwf  = (const float*)d_in[3];
    const float* cbf  = (const float*)d_in[4];
    const float* xpf  = (const float*)d_in[5];
    const float* dtwf = (const float*)d_in[6];
    const float* dtbf = (const float*)d_in[7];
    const float* alf  = (const float*)d_in[8];
    const float* Dfp  = (const float*)d_in[9];
    const float* cwr  = (const float*)d_in[10];
    const float* cbr  = (const float*)d_in[11];
    const float* xpr  = (const float*)d_in[12];
    const float* dtwr = (const float*)d_in[13];
    const float* dtbr = (const float*)d_in[14];
    const float* alr  = (const float*)d_in[15];
    const float* Drp  = (const float*)d_in[16];
    float* out = (float*)d_out;

    float *xz, *xt, *xdbl, *delta, *y, *hs_r, *wi_r, *wo_r, *wxp, *wdt, *dtb;
    cudaGetSymbolAddress((void**)&xz,    g_xz);
    cudaGetSymbolAddress((void**)&xt,    g_xt);
    cudaGetSymbolAddress((void**)&xdbl,  g_xdbl);
    cudaGetSymbolAddress((void**)&delta, g_delta);
    cudaGetSymbolAddress((void**)&y,     g_y);
    cudaGetSymbolAddress((void**)&hs_r,  g_hs_r);
    cudaGetSymbolAddress((void**)&wi_r,  g_wi_r);
    cudaGetSymbolAddress((void**)&wo_r,  g_wo_r);
    cudaGetSymbolAddress((void**)&wxp,   g_wxp);
    cudaGetSymbolAddress((void**)&wdt,   g_wdt);
    cudaGetSymbolAddress((void**)&dtb,   g_dtb);

    cudaFuncSetAttribute(tf32_gemm,
                         cudaFuncAttributeMaxDynamicSharedMemorySize, GEMM_SMEM);

    const size_t dir_di = (size_t)BB * LL * DI;
    const size_t dir_xp = (size_t)BB * LL * XDP;

    // 0. prep (incl. zero-padded dt weights K=64)
    prep_kernel<<<2048, 256>>>(hs, wi, wo, xpf, xpr, dtwf, dtwr, dtbf, dtbr,
                               hs_r, wi_r, wo_r, wxp, wdt, dtb, y, xdbl, out);

    // 1. shared in_proj: xz = hs @ wi^T  (2048 x 3072 x 768)
    tf32_gemm<<<dim3(2 * DI / 64, MTOK / 64, 1), 128, GEMM_SMEM>>>(
        hs_r, 0, wi_r, 0, nullptr, 0, xz, 0, MTOK, 2 * DI, DM, DM, 0, 1);

    // 2. depthwise conv + silu, both dirs
    long total = (long)2 * BB * LL * DI;
    conv_silu_kernel<<<(unsigned)((total + 255) / 256), 256>>>(
        xz, cwf, cbf, cwr, cbr, xt);

    // 3. x_proj, padded N=128, both dirs, split-K x4
    tf32_gemm<<<dim3(XDP / 64, MTOK / 64, 2 * 4), 128, GEMM_SMEM>>>(
        xt, dir_di, wxp, (size_t)XDP * DI, nullptr, 0,
        xdbl, dir_xp, MTOK, XDP, DI, DI, 0, 4);

    // 4. dt projection + softplus, both dirs (K padded to 64, lda=128)
    tf32_gemm<<<dim3(DI / 64, MTOK / 64, 2), 128, GEMM_SMEM>>>(
        xdbl, dir_xp, wdt, (size_t)DI * KDT, dtb, (size_t)DI,
        delta, dir_di, MTOK, DI, KDT, XDP, 1, 1);

    // 5. selective scan v4 (smem partials, no shfl) + gate; atomic y_f + y_r
    scan_kernel<<<dim3(DI / 8, BB, 2), 128>>>(
        xz, xt, xdbl, delta, alf, Dfp, alr, Drp, y);

    // 6. shared out_proj on accumulated y, split-K x3
    tf32_gemm<<<dim3(DM / 64, MTOK / 64, 3), 128, GEMM_SMEM>>>(
        y, 0, wo_r, 0, nullptr, 0, out, 0, MTOK, DM, DI, DI, 0, 3);
}